// round 17
// baseline (speedup 1.0000x reference)
#include <cuda_runtime.h>

#define T_STEPS 10
#define B_SZ    32
#define CIN     3
#define COUT    64
#define SPAT    4096            // 64*64
#define N_THR   (T_STEPS * COUT)
#define DECAY   0.2f
#define INH     1.625f
#define KC      4.6166241f      /* 3.2 * log2(e) */

// Scratch: conv results, CHANNEL-LAST layout (t, b, sp, c).  335.5 MB
__device__ float    g_i[T_STEPS * B_SZ * SPAT * COUT];
__device__ unsigned g_thr_keys[N_THR];   // zero-init at load; self-reset each run
__device__ float4   g_thrv[N_THR];       // {thr, INH*thr, 8*log2e/thr, 0}

// ---- packed f32x2 add (2-operand: rt=2, exact per-component IEEE rn) ------
__device__ __forceinline__ unsigned long long add2(unsigned long long a,
                                                   unsigned long long b) {
    unsigned long long d;
    asm("add.rn.f32x2 %0, %1, %2;" : "=l"(d) : "l"(a), "l"(b));
    return d;
}
__device__ __forceinline__ void upk2(unsigned long long v, float& lo, float& hi) {
    asm("mov.b64 {%0,%1}, %2;" : "=f"(lo), "=f"(hi) : "l"(v));
}

// ---------------------------------------------------------------------------
// Conv 3x3, stride 1, pad 1, binary-input table conv. R17: packed code
// registers (R16) + 3-slot code rotation (R15) -> only 3 new code extractions
// per output; tap bases are LDS immediate offsets. Lookups predicated on
// code!=0 (cz != lp). Bit-exact vs R14/R15/R16 (same table, same add tree).

#define TBL64(off) (*(const unsigned long long*)((const char*)W8 + (off)))

// SA = kx0 slot, SB = kx1 slot, SC = slot receiving the NEW column (kx2).
// RN/SH: packed u64 + shift for the new column's code. C_: output column.
#define STEPX(SA, SB, SC, RN, SH, C_) do {                                    \
    SC[0] = ((unsigned)((RN)[0] >> (SH)) & 7u) * 256u + lp;                   \
    SC[1] = ((unsigned)((RN)[1] >> (SH)) & 7u) * 256u + lp;                   \
    SC[2] = ((unsigned)((RN)[2] >> (SH)) & 7u) * 256u + lp;                   \
    unsigned long long t0_ = 0ull, t1_ = 0ull, t2_ = 0ull, t3_ = 0ull,        \
                       t4_ = 0ull, t5_ = 0ull, t6_ = 0ull, t7_ = 0ull,        \
                       t8_ = 0ull;                                            \
    if (SA[0] != lp) t0_ = TBL64(SA[0]);                                      \
    if (SB[0] != lp) t1_ = TBL64(SB[0] + 2048);                               \
    if (SC[0] != lp) t2_ = TBL64(SC[0] + 4096);                               \
    if (SA[1] != lp) t3_ = TBL64(SA[1] + 6144);                               \
    if (SB[1] != lp) t4_ = TBL64(SB[1] + 8192);                               \
    if (SC[1] != lp) t5_ = TBL64(SC[1] + 10240);                              \
    if (SA[2] != lp) t6_ = TBL64(SA[2] + 12288);                              \
    if (SB[2] != lp) t7_ = TBL64(SB[2] + 14336);                              \
    if (SC[2] != lp) t8_ = TBL64(SC[2] + 16384);                              \
    unsigned long long s_ = add2(add2(add2(t0_, t1_), add2(t2_, t3_)),        \
                                 add2(add2(t4_, t5_), add2(t6_, t7_)));       \
    s_ = add2(s_, t8_);                                                       \
    float v0_, v1_;                                                           \
    upk2(s_, v0_, v1_);                                                       \
    gp[sprow + (C_) * 32 + tx] = make_float2(v0_, v1_);                       \
    mx0 = fmaxf(mx0, v0_);                                                    \
    mx1 = fmaxf(mx1, v1_);                                                    \
} while (0)

__global__ void __launch_bounds__(128) conv_kernel(const float* __restrict__ x,
                                                   const float* __restrict__ Wt) {
    __shared__ __align__(16) float W8[9 * 8 * COUT];   // 18 KB: [tap][code][co]
    __shared__ float              ws[COUT * 27];       // raw weights
    __shared__ unsigned char      codep[18][36];       // plain codes 0..7
    __shared__ unsigned long long crow[18][6];         // packed: 8 codes/u64
    __shared__ unsigned           smax[COUT][4];

    const int tb  = blockIdx.z;              // t*B + b
    const int t   = tb >> 5;
    const int tx  = threadIdx.x;             // lane -> channels 2tx, 2tx+1
    const int wid = threadIdx.y;             // 4 warps -> 4 row groups
    const int tid = wid * 32 + tx;

    // phase A: raw weights + plain code plane
    for (int idx = tid; idx < COUT * 27; idx += 128) ws[idx] = Wt[idx];

    const float* xb = x + tb * (CIN * SPAT);
    const int y0 = blockIdx.y * 16;
    const int x0 = blockIdx.x * 32;
    for (int idx = tid; idx < 18 * 34; idx += 128) {
        int yy = idx / 34;
        int xx = idx - yy * 34;
        int gy = y0 + yy - 1, gx = x0 + xx - 1;
        unsigned char code = 0;
        if ((unsigned)gy < 64u && (unsigned)gx < 64u) {
            const int o = gy * 64 + gx;
            code = (unsigned char)((xb[o] != 0.f ? 1 : 0)
                 | (xb[SPAT + o] != 0.f ? 2 : 0)
                 | (xb[2 * SPAT + o] != 0.f ? 4 : 0));
        }
        codep[yy][xx] = code;
    }
    __syncthreads();

    // phase B: W8 table + packed code rows
    for (int e = tid; e < 9 * 8 * COUT; e += 128) {
        const int tap  = e >> 9;
        const int code = (e >> 6) & 7;
        const int co   = e & 63;
        const float wa = ws[co * 27 + tap];
        const float wb = ws[co * 27 + 9 + tap];
        const float wc = ws[co * 27 + 18 + tap];
        float v = ((code & 1) ? wa : 0.f) + ((code & 2) ? wb : 0.f);
        v += ((code & 4) ? wc : 0.f);
        W8[e] = v;
    }
    for (int e = tid; e < 18 * 6; e += 128) {
        const int yy = e / 6, g = e - (e / 6) * 6;
        unsigned long long v = 0ull;
#pragma unroll
        for (int j = 0; j < 8; j++) {
            const int col = 8 * g + j;
            if (col < 34) v |= (unsigned long long)codep[yy][col] << (8 * j);
        }
        crow[yy][g] = v;
    }
    __syncthreads();

    const unsigned lp = tx * 8;              // channel-pair byte offset

    float2* gp = (float2*)g_i + (long)tb * (SPAT * 32);
    float mx0 = -1e30f, mx1 = -1e30f;

#pragma unroll 1
    for (int rr = 0; rr < 4; rr++) {
        const int row = 4 * wid + rr;                       // tile row 0..15
        const int sprow = ((y0 + row) * 64 + x0) * 32;      // float2 base

        unsigned long long rA[3], rB[3];
        unsigned c0[3], c1[3], c2[3];                       // slot arrays [ky]
#pragma unroll
        for (int k = 0; k < 3; k++) {
            rA[k] = crow[row + k][0];
            rB[k] = crow[row + k][1];
        }
#pragma unroll
        for (int k = 0; k < 3; k++) {
            c0[k] = ((unsigned)(rA[k]) & 7u) * 256u + lp;        // col 0
            c1[k] = ((unsigned)(rA[k] >> 8) & 7u) * 256u + lp;   // col 1
        }

        // block 0: C = 0..7 (phases 0,1,2,...)
        STEPX(c0, c1, c2, rA, 16, 0);
        STEPX(c1, c2, c0, rA, 24, 1);
        STEPX(c2, c0, c1, rA, 32, 2);
        STEPX(c0, c1, c2, rA, 40, 3);
        STEPX(c1, c2, c0, rA, 48, 4);
        STEPX(c2, c0, c1, rA, 56, 5);
        STEPX(c0, c1, c2, rB, 0,  6);
        STEPX(c1, c2, c0, rB, 8,  7);
#pragma unroll
        for (int k = 0; k < 3; k++) { rA[k] = rB[k]; rB[k] = crow[row + k][2]; }

        // block 1: C = 8..15 (phases 2,0,1,...)
        STEPX(c2, c0, c1, rA, 16, 8);
        STEPX(c0, c1, c2, rA, 24, 9);
        STEPX(c1, c2, c0, rA, 32, 10);
        STEPX(c2, c0, c1, rA, 40, 11);
        STEPX(c0, c1, c2, rA, 48, 12);
        STEPX(c1, c2, c0, rA, 56, 13);
        STEPX(c2, c0, c1, rB, 0,  14);
        STEPX(c0, c1, c2, rB, 8,  15);
#pragma unroll
        for (int k = 0; k < 3; k++) { rA[k] = rB[k]; rB[k] = crow[row + k][3]; }

        // block 2: C = 16..23 (phases 1,2,0,...)
        STEPX(c1, c2, c0, rA, 16, 16);
        STEPX(c2, c0, c1, rA, 24, 17);
        STEPX(c0, c1, c2, rA, 32, 18);
        STEPX(c1, c2, c0, rA, 40, 19);
        STEPX(c2, c0, c1, rA, 48, 20);
        STEPX(c0, c1, c2, rA, 56, 21);
        STEPX(c1, c2, c0, rB, 0,  22);
        STEPX(c2, c0, c1, rB, 8,  23);
#pragma unroll
        for (int k = 0; k < 3; k++) { rA[k] = rB[k]; rB[k] = crow[row + k][4]; }

        // block 3: C = 24..31 (phases 0,1,2,...)
        STEPX(c0, c1, c2, rA, 16, 24);
        STEPX(c1, c2, c0, rA, 24, 25);
        STEPX(c2, c0, c1, rA, 32, 26);
        STEPX(c0, c1, c2, rA, 40, 27);
        STEPX(c1, c2, c0, rA, 48, 28);
        STEPX(c2, c0, c1, rA, 56, 29);
        STEPX(c0, c1, c2, rB, 0,  30);
        STEPX(c1, c2, c0, rB, 8,  31);
    }

    // per-(t,c) max: order-preserving keys, block reduce, one global atomic
    unsigned u0 = __float_as_uint(mx0);
    unsigned k0 = ((int)u0 < 0) ? ~u0 : (u0 | 0x80000000u);
    unsigned u1 = __float_as_uint(mx1);
    unsigned k1 = ((int)u1 < 0) ? ~u1 : (u1 | 0x80000000u);
    smax[2 * tx][wid]     = k0;
    smax[2 * tx + 1][wid] = k1;
    __syncthreads();
    if (tid < COUT) {
        unsigned m = smax[tid][0];
        m = max(m, smax[tid][1]); m = max(m, smax[tid][2]); m = max(m, smax[tid][3]);
        atomicMax(&g_thr_keys[t * COUT + tid], m);
    }
}

// ---------------------------------------------------------------------------
// Decode per-(t,c) max keys -> threshold vectors, then RESET the keys so the
// next graph replay starts from zero.
__global__ void finalize_thr() {
    int i = blockIdx.x * blockDim.x + threadIdx.x;
    if (i < N_THR) {
        unsigned k = g_thr_keys[i];
        unsigned u = (k & 0x80000000u) ? (k & 0x7FFFFFFFu) : ~k;
        float thr  = __uint_as_float(u) + 1e-4f;
        float zs   = 11.541560f / thr;        // 8*log2(e)/thr
        g_thrv[i]  = make_float4(thr, INH * thr, zs, 0.f);
        g_thr_keys[i] = 0u;                   // self-reset for next replay
    }
}

// ---------------------------------------------------------------------------
// LIF + ASF + WTA + inhibition (R10/R12, proven): warp-per-pixel on
// channel-last data, lane owns channels 2tx/2tx+1 (one coalesced float2 load
// per t), WTA via 2 REDUX ops, mem in regs. No barriers in the t-loop.
__global__ void __launch_bounds__(1024) lif_kernel(float* __restrict__ out) {
    __shared__ float2 sth[320], sih[320], szs[320];  // [t*32 + pair]
    __shared__ int    swz[32][11];                   // [pixel][t], pad 11

    const int tx  = threadIdx.x;         // lane -> channel pair
    const int ty  = threadIdx.y;         // warp -> pixel
    const int tid = ty * 32 + tx;
    const int b   = blockIdx.x >> 7;     // 128 blocks per batch image
    const int spb = (blockIdx.x & 127) * 32;

    if (tid < 320) {
        int t = tid >> 5, p = tid & 31;
        float4 a = g_thrv[t * COUT + 2 * p];
        float4 c = g_thrv[t * COUT + 2 * p + 1];
        sth[tid] = make_float2(a.x, c.x);
        sih[tid] = make_float2(a.y, c.y);
        szs[tid] = make_float2(a.z, c.z);
    }
    __syncthreads();

    const int sp    = spb + ty;
    const int c0    = 2 * tx, c1 = 2 * tx + 1;
    const float2* ip = (const float2*)g_i;
    const int pbase = (b * SPAT + sp) * 32 + tx;     // float2 index
    const int tstep = B_SZ * SPAT * 32;              // float2 per timestep

    float2 b0 = ip[pbase];
    float2 b1 = ip[pbase + tstep];
    float m0 = 0.f, m1 = 0.f;

#pragma unroll
    for (int t = 0; t < T_STEPS; t++) {
        const float2 iv = (t & 1) ? b1 : b0;
        if (t + 2 < T_STEPS) {                       // depth-2 prefetch
            if (t & 1) b1 = ip[pbase + (t + 2) * tstep];
            else       b0 = ip[pbase + (t + 2) * tstep];
        }
        const float2 th = sth[t * 32 + tx];
        const float2 ih = sih[t * 32 + tx];
        const float2 zs = szs[t * 32 + tx];

        // fast ASF: thr / (1 + exp2(KC - cur*zs))
        float zn0 = fmaf(fmaxf(iv.x, 0.f), -zs.x, KC);
        float zn1 = fmaf(fmaxf(iv.y, 0.f), -zs.y, KC);
        float e0, e1, q0, q1;
        asm("ex2.approx.f32 %0, %1;" : "=f"(e0) : "f"(zn0));
        asm("ex2.approx.f32 %0, %1;" : "=f"(e1) : "f"(zn1));
        asm("rcp.approx.f32 %0, %1;" : "=f"(q0) : "f"(1.f + e0));
        asm("rcp.approx.f32 %0, %1;" : "=f"(q1) : "f"(1.f + e1));

        m0 = fmaf(m0, DECAY, th.x * q0);
        m1 = fmaf(m1, DECAY, th.y * q1);

        const int   s0i = m0 > th.x ? 1 : 0;
        const int   s1i = m1 > th.y ? 1 : 0;
        const float sc0 = s0i ? m0 : 0.f;
        const float sc1 = s1i ? m1 : 0.f;

        // per-lane candidate; lower channel wins ties (argmax-first semantics)
        float bs; int bi;
        if (sc0 >= sc1) { bs = sc0; bi = (c0 << 1) | s0i; }
        else            { bs = sc1; bi = (c1 << 1) | s1i; }

        unsigned ub   = __float_as_uint(bs);
        unsigned key  = ((int)ub < 0) ? ~ub : (ub | 0x80000000u);
        unsigned mk   = __reduce_max_sync(0xffffffffu, key);
        unsigned cand = (key == mk) ? (unsigned)bi : 0x7fffffffu;
        const int wz  = (int)__reduce_min_sync(0xffffffffu, cand);

        const int   wc  = wz >> 1;
        const float any = (float)(wz & 1);            // winner's spike -> any_sp

        const float sn0 = (wc == c0) ? (float)s0i : 0.f;
        const float sn1 = (wc == c1) ? (float)s1i : 0.f;

        m0 = (sn0 > 0.f) ? 0.f : fmaf(-ih.x, any, m0);
        m1 = (sn1 > 0.f) ? 0.f : fmaf(-ih.y, any, m1);

        if (tx == 0) swz[ty][t] = wz;
    }
    __syncthreads();

    // store phase: reference layout (t,b,c,h,w); lanes = pixels (coalesced)
    const int obase = (b * COUT) * SPAT + spb + tx;
    const int ostep = B_SZ * COUT * SPAT;
#pragma unroll
    for (int t = 0; t < T_STEPS; t++) {
        const int w = swz[tx][t];
        out[obase + t * ostep + ty * SPAT]        = (w == ((ty << 1) | 1))        ? 1.f : 0.f;
        out[obase + t * ostep + (ty + 32) * SPAT] = (w == (((ty + 32) << 1) | 1)) ? 1.f : 0.f;
    }
}

// ---------------------------------------------------------------------------
extern "C" void kernel_launch(void* const* d_in, const int* in_sizes, int n_in,
                              void* d_out, int out_size) {
    const float* x = (const float*)d_in[0];
    const float* W = (const float*)d_in[1];
    if (n_in >= 2 && in_sizes[0] == COUT * CIN * 9) {  // defensive order swap
        const float* tmp = x; x = W; W = tmp;
    }

    dim3 cb(32, 4);
    dim3 cg(2, 4, T_STEPS * B_SZ);
    conv_kernel<<<cg, cb>>>(x, W);

    finalize_thr<<<1, N_THR>>>();

    lif_kernel<<<(B_SZ * SPAT) / 32, dim3(32, 32)>>>((float*)d_out);
}